// round 11
// baseline (speedup 1.0000x reference)
#include <cuda_runtime.h>
#include <cuda_bf16.h>
#include <math.h>

#define Bc   8
#define Lc   256
#define Dc   128
#define Hc   4
#define HDc  32
#define NROW (Bc*Lc)      // 2048
#define RQ   8            // rows per block in qkv GEMM
#define RF   4            // rows per block in ffn
#define NTAU 257
#define CVTB 129          // blocks for timeV bf16 conversion (NTAU*Dc/256)

#define TQ2  4            // queries per attention block
#define CH   64           // key chunk
#define PADK 132          // floats per padded smem row (33 float4)
#define NEGV (-4294967295.0f)
#define SCALE 0.17677669529663689f
// dyn smem floats: sKV 8448 + sQ 512 + sS 4096 = 13056; ints: tm 1024
#define SMEM_ATTN (13056*4 + 1024*4)

// ---------------- device scratch ----------------
__device__ __align__(16) float g_seqs[NROW*Dc];
__device__ __align__(16) float g_qin [NROW*Dc];
__device__ __align__(16) float g_Q   [NROW*Dc];   // pre-scaled by 1/sqrt(HD)
__device__ __align__(16) float g_Kc  [NROW*Dc];   // K + bk + posK
__device__ __align__(16) float g_Vc  [NROW*Dc];   // V + bv + posV
__device__ __align__(16) float g_dqt [NROW*NTAU*4]; // Qs . timeK[tau], per head
__device__ __align__(16) __nv_bfloat16 g_tVb[NTAU*Dc]; // bf16 copy of timeV

// ---------------- K0: embedding + LN1(layer 0); tail blocks convert timeV ----------------
__global__ void __launch_bounds__(128) k_embed(const int* __restrict__ log_seqs,
                        const float* __restrict__ item_emb,
                        const float* __restrict__ g1, const float* __restrict__ b1,
                        const float* __restrict__ timeV) {
    __shared__ float r1[4], r2[4];
    int row = blockIdx.x, t = threadIdx.x;
    if (row >= NROW) { // timeV bf16 conversion tail
        int i = (row - NROW)*256 + t*2;
        if (i < NTAU*Dc) {
            float2 v = *(const float2*)&timeV[i];
            *(__nv_bfloat162*)&g_tVb[i] = __floats2bfloat162_rn(v.x, v.y);
        }
        return;
    }
    int warp = t >> 5, lane = t & 31;
    int idx = log_seqs[row];
    float v = (idx == 0) ? 0.f
                         : item_emb[idx*Dc + t] * 11.313708498984761f; // sqrt(128)
    g_seqs[row*Dc + t] = v;
    float s = v, ss = v*v;
    #pragma unroll
    for (int o = 16; o >= 1; o >>= 1) {
        s  += __shfl_xor_sync(0xffffffffu, s,  o);
        ss += __shfl_xor_sync(0xffffffffu, ss, o);
    }
    if (lane == 0) { r1[warp] = s; r2[warp] = ss; }
    __syncthreads();
    float tot  = r1[0]+r1[1]+r1[2]+r1[3];
    float tots = r2[0]+r2[1]+r2[2]+r2[3];
    float m = tot * (1.f/Dc);
    float inv = rsqrtf(tots * (1.f/Dc) - m*m + 1e-8f);
    g_qin[row*Dc + t] = (v - m) * inv * g1[t] + b1[t];
}

// ---------------- K1: QKV projections (blockIdx.y selects matrix) ----------------
__global__ void __launch_bounds__(128) k_qkv(
                      const float* __restrict__ Wq, const float* __restrict__ Wk,
                      const float* __restrict__ Wv,
                      const float* __restrict__ bq, const float* __restrict__ bk,
                      const float* __restrict__ bv,
                      const float* __restrict__ posK, const float* __restrict__ posV) {
    __shared__ __align__(16) float s_x[RQ][Dc];
    int t = threadIdx.x;
    int mat = blockIdx.y;
    int row0 = blockIdx.x * RQ;

    const float* X = (mat == 0) ? g_qin : g_seqs;
    const float* W = (mat == 0) ? Wq : (mat == 1) ? Wk : Wv;
    const float* B = (mat == 0) ? bq : (mat == 1) ? bk : bv;
    float*       O = (mat == 0) ? g_Q : (mat == 1) ? g_Kc : g_Vc;
    const float* P = (mat == 1) ? posK : posV;

    for (int i = t; i < RQ*Dc; i += 128)
        ((float*)s_x)[i] = X[row0*Dc + i];
    __syncthreads();

    float acc[RQ];
    #pragma unroll
    for (int r = 0; r < RQ; ++r) acc[r] = 0.f;

    for (int k = 0; k < Dc; k += 4) {
        float w0 = W[(k+0)*Dc + t], w1 = W[(k+1)*Dc + t];
        float w2 = W[(k+2)*Dc + t], w3 = W[(k+3)*Dc + t];
        #pragma unroll
        for (int r = 0; r < RQ; ++r) {
            float4 x = *(const float4*)&s_x[r][k];
            acc[r] = fmaf(x.x,w0, fmaf(x.y,w1, fmaf(x.z,w2, fmaf(x.w,w3, acc[r]))));
        }
    }

    float bb = B[t];
    #pragma unroll
    for (int r = 0; r < RQ; ++r) {
        int row = row0 + r;
        if (mat == 0) {
            O[row*Dc + t] = (acc[r] + bb) * SCALE;   // fold 1/sqrt(HD) into Q
        } else {
            O[row*Dc + t] = acc[r] + bb + P[(row & (Lc-1))*Dc + t];
        }
    }
}

// ---------------- K1c: dqt[row,tau,h] = Qs[row,h,:] . timeK[tau,h,:] ----------------
// thread = (tau, head); timeK segment in registers; Q broadcast from smem.
// QTROWS=16 -> grid 640 (~4.3 blocks/SM); launch_bounds forces 4 blocks/SM.
// Row loop unrolled x2 -> 4 independent FMA chains.
#define QTROWS 16
__global__ void __launch_bounds__(256, 4) k_qt(const float* __restrict__ timeK) {
    __shared__ __align__(16) float sQ[QTROWS*128];   // 8 KB
    int t = threadIdx.x;
    int w = t >> 5, lane = t & 31;
    int h = w & 3;
    int tau = blockIdx.y*64 + (w >> 2)*32 + lane;
    int r0 = blockIdx.x * QTROWS;
    bool valid = (tau < NTAU);

    float4 tr[8];
    if (valid) {
        const float4* src = (const float4*)&timeK[tau*128 + h*32];
        #pragma unroll
        for (int j = 0; j < 8; ++j) tr[j] = src[j];
    }

    { // stage 16 Q rows (coalesced): 512 float4
        const float4* src = (const float4*)&g_Q[r0*128];
        float4* dst = (float4*)sQ;
        dst[t] = src[t];
        dst[t + 256] = src[t + 256];
    }
    __syncthreads();
    if (valid) {
        for (int r = 0; r < QTROWS; r += 2) {
            const float4* qa = (const float4*)&sQ[r*128 + h*32];       // broadcast
            const float4* qb = (const float4*)&sQ[(r+1)*128 + h*32];   // broadcast
            float a0 = 0.f, a1 = 0.f, b0 = 0.f, b1 = 0.f;
            #pragma unroll
            for (int j = 0; j < 8; j += 2) {
                float4 qa0 = qa[j], qa1 = qa[j+1];
                float4 qb0 = qb[j], qb1 = qb[j+1];
                a0 += tr[j  ].x*qa0.x + tr[j  ].y*qa0.y + tr[j  ].z*qa0.z + tr[j  ].w*qa0.w;
                a1 += tr[j+1].x*qa1.x + tr[j+1].y*qa1.y + tr[j+1].z*qa1.z + tr[j+1].w*qa1.w;
                b0 += tr[j  ].x*qb0.x + tr[j  ].y*qb0.y + tr[j  ].z*qb0.z + tr[j  ].w*qb0.w;
                b1 += tr[j+1].x*qb1.x + tr[j+1].y*qb1.y + tr[j+1].z*qb1.z + tr[j+1].w*qb1.w;
            }
            g_dqt[((size_t)(r0 + r    )*NTAU + tau)*4 + h] = a0 + a1;
            g_dqt[((size_t)(r0 + r + 1)*NTAU + tau)*4 + h] = b0 + b1;
        }
    }
}

// ---------------- K2: tiled attention (pad-free, causal-truncated) ----------------
// Pad-query rows produce garbage here by design: k_ffn zeroes them before any
// consumer reads them, and attention contributions are strictly row-local.
__global__ void __launch_bounds__(256) k_attn(const int* __restrict__ time_mat) {
    extern __shared__ __align__(16) char smem_raw[];
    float* sKV = (float*)smem_raw;                 // CH*PADK = 8448
    float* sQ  = sKV + 8448;                       // TQ2*128 = 512
    float* sS  = sQ  + 512;                        // TQ2*4*256 = 4096
    int*   s_tm = (int*)(sS + 4096);               // TQ2*256 = 1024

    int t = threadIdx.x;                           // 256
    int b  = blockIdx.x >> 6;
    int q0 = (blockIdx.x & 63) * TQ2;
    int row0 = b*Lc + q0;
    int brow = b*Lc;

    { // Q tile: 512 floats = 128 float4
        if (t < 128) {
            const float4* src = (const float4*)&g_Q[row0*128];
            ((float4*)sQ)[t] = src[t];
        }
    }
    { // tm tile: 1024 ints = 256 int4
        const int4* src = (const int4*)&time_mat[row0*256];
        ((int4*)s_tm)[t] = src[t];
    }
    { // init sS = NEGV
        float4 negv = make_float4(NEGV, NEGV, NEGV, NEGV);
        float4* p = (float4*)sS;
        #pragma unroll
        for (int i = 0; i < 4; ++i) p[t + 256*i] = negv;
    }
    __syncthreads();

    int nkt = ((q0 + TQ2 - 1) >> 6) + 1;

    // ---- pass 1: scores (Q pre-scaled, causal only) ----
    {
        int q = t >> 6, kl = t & 63;
        for (int kt = 0; kt < nkt; ++kt) {
            int k0 = kt * CH;
            { // coalesced load Kc chunk: 2048 float4
                const float4* src = (const float4*)&g_Kc[(brow + k0)*128];
                float4* dst = (float4*)sKV;
                #pragma unroll
                for (int j = 0; j < 8; ++j) {
                    int f4 = t + 256*j;
                    dst[(f4 >> 5)*33 + (f4 & 31)] = src[f4];
                }
            }
            __syncthreads();
            int kg = k0 + kl;
            if (kg <= q0 + q) {
                const float4* kr = (const float4*)&sKV[kl*PADK];
                const float4* qr = (const float4*)&sQ[q*128];   // broadcast
                float sc[4] = {0.f, 0.f, 0.f, 0.f};
                #pragma unroll
                for (int j = 0; j < 32; ++j) {
                    float4 kv = kr[j], qv = qr[j];
                    sc[j >> 3] += kv.x*qv.x + kv.y*qv.y + kv.z*qv.z + kv.w*qv.w;
                }
                int tau = s_tm[q*256 + kg];
                float4 dq = *(const float4*)&g_dqt[((size_t)(row0 + q)*NTAU + tau)*4];
                sS[(q*4+0)*256 + kg] = sc[0] + dq.x;
                sS[(q*4+1)*256 + kg] = sc[1] + dq.y;
                sS[(q*4+2)*256 + kg] = sc[2] + dq.z;
                sS[(q*4+3)*256 + kg] = sc[3] + dq.w;
            }
            __syncthreads();
        }
    }

    // ---- pass 2: softmax (16 rows of 256; each warp handles 2 rows) ----
    {
        int w = t >> 5, lane = t & 31;
        #pragma unroll
        for (int j = 0; j < 2; ++j) {
            float* p = sS + (w + j*8)*256;
            float x[8];
            float mx = -3.4e38f;
            #pragma unroll
            for (int i = 0; i < 8; ++i) { x[i] = p[lane + 32*i]; mx = fmaxf(mx, x[i]); }
            #pragma unroll
            for (int o = 16; o >= 1; o >>= 1)
                mx = fmaxf(mx, __shfl_xor_sync(0xffffffffu, mx, o));
            float s = 0.f;
            #pragma unroll
            for (int i = 0; i < 8; ++i) { x[i] = expf(x[i] - mx); s += x[i]; }
            #pragma unroll
            for (int o = 16; o >= 1; o >>= 1)
                s += __shfl_xor_sync(0xffffffffu, s, o);
            float inv = 1.f / s;
            #pragma unroll
            for (int i = 0; i < 8; ++i) p[lane + 32*i] = x[i] * inv;
        }
    }
    __syncthreads();

    // ---- pass 3: out = A @ (Vc + timeV[bf16]); 1 q x 2 cols per thread ----
    {
        int colp = (t & 63) * 2;      // even column
        int q    = t >> 6;            // warp-uniform
        int h    = colp >> 5;
        int kend = q0 + q + 1;        // exact causal limit
        const float* sA = sS + (q*4 + h)*256;
        const int*   tmq = s_tm + q*256;
        float acc0 = 0.f, acc1 = 0.f;
        for (int kt = 0; kt < nkt; ++kt) {
            int k0 = kt * CH;
            __syncthreads();
            { // coalesced load Vc chunk
                const float4* src = (const float4*)&g_Vc[(brow + k0)*128];
                float4* dst = (float4*)sKV;
                #pragma unroll
                for (int j = 0; j < 8; ++j) {
                    int f4 = t + 256*j;
                    dst[(f4 >> 5)*33 + (f4 & 31)] = src[f4];
                }
            }
            __syncthreads();
            int ke = kend - k0; if (ke > CH) ke = CH;
            for (int k = 0; k < ke; ++k) {
                int kg = k0 + k;
                float2 v2 = *(const float2*)&sKV[k*PADK + colp];
                float a = sA[kg];                               // broadcast
                int tau = tmq[kg];                              // broadcast
                __nv_bfloat162 tv2 = *(const __nv_bfloat162*)&g_tVb[tau*128 + colp];
                float2 tvf = __bfloat1622float2(tv2);
                acc0 = fmaf(a, v2.x + tvf.x, acc0);
                acc1 = fmaf(a, v2.y + tvf.y, acc1);
            }
        }
        int idx = (row0 + q)*128 + colp;
        float2 qi = *(const float2*)&g_qin[idx];
        float2 o2 = make_float2(qi.x + acc0, qi.y + acc1);
        *(float2*)&g_seqs[idx] = o2;
    }
}

// ---------------- K3: LN2 + FFN + residual + pad-mask (+ LN1 of next layer) ----------------
__global__ void __launch_bounds__(128) k_ffn(const int* __restrict__ log_seqs,
                      const float* __restrict__ ln2_g, const float* __restrict__ ln2_b,
                      const float* __restrict__ W1, const float* __restrict__ b1,
                      const float* __restrict__ W2, const float* __restrict__ b2,
                      const float* __restrict__ ng, const float* __restrict__ nb) {
    __shared__ __align__(16) float s_y[RF][Dc];
    __shared__ __align__(16) float s_h[RF][Dc];
    __shared__ float s_mean[RF], s_inv[RF];
    __shared__ int   s_pad[RF];
    int t = threadIdx.x;
    int row0 = blockIdx.x * RF;
    int r = t >> 5, lane = t & 31;

    for (int i = t; i < RF*Dc; i += 128)
        ((float*)s_h)[i] = g_seqs[row0*Dc + i];
    if (t < RF) s_pad[t] = (log_seqs[row0 + t] == 0);
    __syncthreads();

    {
        float4 v4 = *(const float4*)&s_h[r][lane*4];
        float s  = v4.x + v4.y + v4.z + v4.w;
        float ss = v4.x*v4.x + v4.y*v4.y + v4.z*v4.z + v4.w*v4.w;
        #pragma unroll
        for (int o = 16; o >= 1; o >>= 1) {
            s  += __shfl_xor_sync(0xffffffffu, s,  o);
            ss += __shfl_xor_sync(0xffffffffu, ss, o);
        }
        if (lane == 0) {
            float m = s * (1.f/Dc);
            float var = ss * (1.f/Dc) - m*m;
            s_mean[r] = m;
            s_inv[r]  = rsqrtf(var + 1e-8f);
        }
    }
    __syncthreads();

    float g = ln2_g[t], bb = ln2_b[t];
    #pragma unroll
    for (int rr = 0; rr < RF; ++rr)
        s_y[rr][t] = (s_h[rr][t] - s_mean[rr]) * s_inv[rr] * g + bb;
    __syncthreads();

    float a1[RF];
    #pragma unroll
    for (int rr = 0; rr < RF; ++rr) a1[rr] = 0.f;
    for (int k = 0; k < Dc; k += 4) {
        float w0=W1[(k+0)*Dc+t], w1=W1[(k+1)*Dc+t], w2=W1[(k+2)*Dc+t], w3=W1[(k+3)*Dc+t];
        #pragma unroll
        for (int rr = 0; rr < RF; ++rr) {
            float4 y = *(const float4*)&s_y[rr][k];
            a1[rr] = fmaf(y.x,w0, fmaf(y.y,w1, fmaf(y.z,w2, fmaf(y.w,w3, a1[rr]))));
        }
    }
    float b1v = b1[t];
    __syncthreads();
    #pragma unroll
    for (int rr = 0; rr < RF; ++rr)
        s_h[rr][t] = fmaxf(a1[rr] + b1v, 0.f);
    __syncthreads();

    float a2[RF];
    #pragma unroll
    for (int rr = 0; rr < RF; ++rr) a2[rr] = 0.f;
    for (int k = 0; k < Dc; k += 4) {
        float w0=W2[(k+0)*Dc+t], w1=W2[(k+1)*Dc+t], w2=W2[(k+2)*Dc+t], w3=W2[(k+3)*Dc+t];
        #pragma unroll
        for (int rr = 0; rr < RF; ++rr) {
            float4 h4 = *(const float4*)&s_h[rr][k];
            a2[rr] = fmaf(h4.x,w0, fmaf(h4.y,w1, fmaf(h4.z,w2, fmaf(h4.w,w3, a2[rr]))));
        }
    }
    float b2v = b2[t];
    float vout[RF];
    #pragma unroll
    for (int rr = 0; rr < RF; ++rr) {
        vout[rr] = s_pad[rr] ? 0.f : (s_y[rr][t] + a2[rr] + b2v);
        g_seqs[(row0 + rr)*Dc + t] = vout[rr];
    }

    if (ng) {  // LN1 of next layer, fused
        __syncthreads();
        #pragma unroll
        for (int rr = 0; rr < RF; ++rr) s_h[rr][t] = vout[rr];
        __syncthreads();
        {
            float4 v4 = *(const float4*)&s_h[r][lane*4];
            float s  = v4.x + v4.y + v4.z + v4.w;
            float ss = v4.x*v4.x + v4.y*v4.y + v4.z*v4.z + v4.w*v4.w;
            #pragma unroll
            for (int o = 16; o >= 1; o >>= 1) {
                s  += __shfl_xor_sync(0xffffffffu, s,  o);
                ss += __shfl_xor_sync(0xffffffffu, ss, o);
            }
            if (lane == 0) {
                float m = s * (1.f/Dc);
                float var = ss * (1.f/Dc) - m*m;
                s_mean[r] = m;
                s_inv[r]  = rsqrtf(var + 1e-8f);
            }
        }
        __syncthreads();
        float gg = ng[t], bb2 = nb[t];
        #pragma unroll
        for (int rr = 0; rr < RF; ++rr)
            g_qin[(row0 + rr)*Dc + t] = (s_h[rr][t] - s_mean[rr]) * s_inv[rr] * gg + bb2;
    }
}

// ---------------- K4: final LN + pos/neg logits ----------------
__global__ void __launch_bounds__(128) k_logits(
                         const int* __restrict__ pos_seqs, const int* __restrict__ neg_seqs,
                         const float* __restrict__ item_emb,
                         const float* __restrict__ lnf_g, const float* __restrict__ lnf_b,
                         float* __restrict__ out) {
    __shared__ float r1[4], r2[4];
    int row = blockIdx.x, t = threadIdx.x;
    int warp = t >> 5, lane = t & 31;

    float x = g_seqs[row*Dc + t];
    float s = x, ss = x*x;
    #pragma unroll
    for (int o = 16; o >= 1; o >>= 1) {
        s  += __shfl_xor_sync(0xffffffffu, s,  o);
        ss += __shfl_xor_sync(0xffffffffu, ss, o);
    }
    if (lane == 0) { r1[warp] = s; r2[warp] = ss; }
    __syncthreads();
    float tot  = r1[0]+r1[1]+r1[2]+r1[3];
    float tots = r2[0]+r2[1]+r2[2]+r2[3];
    float m = tot * (1.f/Dc);
    float inv = rsqrtf(tots * (1.f/Dc) - m*m + 1e-8f);
    float f = (x - m) * inv * lnf_g[t] + lnf_b[t];

    int pi = pos_seqs[row], ni = neg_seqs[row];
    float pp = f * item_emb[pi*Dc + t];
    float nn = f * item_emb[ni*Dc + t];
    #pragma unroll
    for (int o = 16; o >= 1; o >>= 1) {
        pp += __shfl_xor_sync(0xffffffffu, pp, o);
        nn += __shfl_xor_sync(0xffffffffu, nn, o);
    }
    __syncthreads();
    if (lane == 0) { r1[warp] = pp; r2[warp] = nn; }
    __syncthreads();
    if (t == 0) {
        out[row]        = r1[0]+r1[1]+r1[2]+r1[3];
        out[NROW + row] = r2[0]+r2[1]+r2[2]+r2[3];
    }
}

// ---------------- launch ----------------
extern "C" void kernel_launch(void* const* d_in, const int* in_sizes, int n_in,
                              void* d_out, int out_size) {
    const int*   log_seqs = (const int*)  d_in[1];
    const int*   time_mat = (const int*)  d_in[2];
    const int*   pos_seqs = (const int*)  d_in[3];
    const int*   neg_seqs = (const int*)  d_in[4];
    const float* item_emb = (const float*)d_in[5];
    const float* posK     = (const float*)d_in[6];
    const float* posV     = (const float*)d_in[7];
    const float* timeK    = (const float*)d_in[8];
    const float* timeV    = (const float*)d_in[9];
    const float* ln1_g    = (const float*)d_in[10];
    const float* ln1_b    = (const float*)d_in[11];
    const float* Wq       = (const float*)d_in[12];
    const float* bq       = (const float*)d_in[13];
    const float* Wk       = (const float*)d_in[14];
    const float* bk       = (const float*)d_in[15];
    const float* Wv       = (const float*)d_in[16];
    const float* bv       = (const float*)d_in[17];
    const float* ln2_g    = (const float*)d_in[18];
    const float* ln2_b    = (const float*)d_in[19];
    const float* W1       = (const float*)d_in[20];
    const float* b1       = (const float*)d_in[21];
    const float* W2       = (const float*)d_in[22];
    const float* b2       = (const float*)d_in[23];
    const float* lnf_g    = (const float*)d_in[24];
    const float* lnf_b    = (const float*)d_in[25];
    float* out = (float*)d_out;

    cudaFuncSetAttribute(k_attn, cudaFuncAttributeMaxDynamicSharedMemorySize, SMEM_ATTN);

    k_embed<<<NROW + CVTB, 128>>>(log_seqs, item_emb, ln1_g, ln1_b, timeV);
    for (int i = 0; i < 2; ++i) {
        dim3 gq(NROW/RQ, 3);
        k_qkv<<<gq, 128>>>(Wq + i*Dc*Dc, Wk + i*Dc*Dc, Wv + i*Dc*Dc,
                           bq + i*Dc, bk + i*Dc, bv + i*Dc, posK, posV);
        dim3 gt(NROW/QTROWS, 5);          // (128, 5) = 640 blocks
        k_qt<<<gt, 256>>>(timeK);
        k_attn<<<NROW/TQ2, 256, SMEM_ATTN>>>(time_mat);
        const float* ng = (i == 0) ? (ln1_g + Dc) : nullptr;
        const float* nb = (i == 0) ? (ln1_b + Dc) : nullptr;
        k_ffn<<<NROW/RF, 128>>>(log_seqs, ln2_g + i*Dc, ln2_b + i*Dc,
                                W1 + i*Dc*Dc, b1 + i*Dc,
                                W2 + i*Dc*Dc, b2 + i*Dc, ng, nb);
    }
    k_logits<<<NROW, 128>>>(pos_seqs, neg_seqs, item_emb, lnf_g, lnf_b, out);
}

// round 13
// speedup vs baseline: 1.1075x; 1.1075x over previous
#include <cuda_runtime.h>
#include <cuda_bf16.h>
#include <math.h>

#define Bc   8
#define Lc   256
#define Dc   128
#define Hc   4
#define HDc  32
#define NROW (Bc*Lc)      // 2048
#define RQ   8            // rows per block in qkv GEMM
#define RF   4            // rows per block in ffn
#define NTAU 257
#define DQR  1028         // floats per g_dqt row: 4 heads * 257 taus
#define CVTB 129          // blocks for timeV bf16 conversion

#define TQ2  4            // queries per attention block
#define CH   64           // key chunk (pass 1 staging)
#define PADK 132          // floats per padded smem row (33 float4)
#define NEGV (-4294967295.0f)
#define SCALE 0.17677669529663689f
// dyn smem floats: sKV 8448 + sQ 512 + sS 4096 = 13056; ints: tm 1024
#define SMEM_ATTN (13056*4 + 1024*4)

// ---------------- device scratch ----------------
__device__ __align__(16) float g_seqs[NROW*Dc];
__device__ __align__(16) float g_qin [NROW*Dc];
__device__ __align__(16) float g_Q   [NROW*Dc];   // pre-scaled by 1/sqrt(HD)
__device__ __align__(16) float g_Kc  [NROW*Dc];   // K + bk + posK
__device__ __align__(16) float g_Vc  [NROW*Dc];   // V + bv + posV
__device__ __align__(16) float g_dqt [NROW*DQR];  // [row][h][tau] layout (coalesced stores)
__device__ __align__(16) __nv_bfloat16 g_tVb[NTAU*Dc]; // bf16 copy of timeV

// ---------------- K0: embedding + LN1(layer 0); tail blocks convert timeV ----------------
__global__ void __launch_bounds__(128) k_embed(const int* __restrict__ log_seqs,
                        const float* __restrict__ item_emb,
                        const float* __restrict__ g1, const float* __restrict__ b1,
                        const float* __restrict__ timeV) {
    __shared__ float r1[4], r2[4];
    int row = blockIdx.x, t = threadIdx.x;
    if (row >= NROW) { // timeV bf16 conversion tail
        int i = (row - NROW)*256 + t*2;
        if (i < NTAU*Dc) {
            float2 v = *(const float2*)&timeV[i];
            *(__nv_bfloat162*)&g_tVb[i] = __floats2bfloat162_rn(v.x, v.y);
        }
        return;
    }
    int warp = t >> 5, lane = t & 31;
    int idx = log_seqs[row];
    float v = (idx == 0) ? 0.f
                         : item_emb[idx*Dc + t] * 11.313708498984761f; // sqrt(128)
    g_seqs[row*Dc + t] = v;
    float s = v, ss = v*v;
    #pragma unroll
    for (int o = 16; o >= 1; o >>= 1) {
        s  += __shfl_xor_sync(0xffffffffu, s,  o);
        ss += __shfl_xor_sync(0xffffffffu, ss, o);
    }
    if (lane == 0) { r1[warp] = s; r2[warp] = ss; }
    __syncthreads();
    float tot  = r1[0]+r1[1]+r1[2]+r1[3];
    float tots = r2[0]+r2[1]+r2[2]+r2[3];
    float m = tot * (1.f/Dc);
    float inv = rsqrtf(tots * (1.f/Dc) - m*m + 1e-8f);
    g_qin[row*Dc + t] = (v - m) * inv * g1[t] + b1[t];
}

// ---------------- K1: QKV projections (blockIdx.y selects matrix) ----------------
__global__ void __launch_bounds__(128) k_qkv(
                      const float* __restrict__ Wq, const float* __restrict__ Wk,
                      const float* __restrict__ Wv,
                      const float* __restrict__ bq, const float* __restrict__ bk,
                      const float* __restrict__ bv,
                      const float* __restrict__ posK, const float* __restrict__ posV) {
    __shared__ __align__(16) float s_x[RQ][Dc];
    int t = threadIdx.x;
    int mat = blockIdx.y;
    int row0 = blockIdx.x * RQ;

    const float* X = (mat == 0) ? g_qin : g_seqs;
    const float* W = (mat == 0) ? Wq : (mat == 1) ? Wk : Wv;
    const float* B = (mat == 0) ? bq : (mat == 1) ? bk : bv;
    float*       O = (mat == 0) ? g_Q : (mat == 1) ? g_Kc : g_Vc;
    const float* P = (mat == 1) ? posK : posV;

    for (int i = t; i < RQ*Dc; i += 128)
        ((float*)s_x)[i] = X[row0*Dc + i];
    __syncthreads();

    float acc[RQ];
    #pragma unroll
    for (int r = 0; r < RQ; ++r) acc[r] = 0.f;

    for (int k = 0; k < Dc; k += 4) {
        float w0 = W[(k+0)*Dc + t], w1 = W[(k+1)*Dc + t];
        float w2 = W[(k+2)*Dc + t], w3 = W[(k+3)*Dc + t];
        #pragma unroll
        for (int r = 0; r < RQ; ++r) {
            float4 x = *(const float4*)&s_x[r][k];
            acc[r] = fmaf(x.x,w0, fmaf(x.y,w1, fmaf(x.z,w2, fmaf(x.w,w3, acc[r]))));
        }
    }

    float bb = B[t];
    #pragma unroll
    for (int r = 0; r < RQ; ++r) {
        int row = row0 + r;
        if (mat == 0) {
            O[row*Dc + t] = (acc[r] + bb) * SCALE;   // fold 1/sqrt(HD) into Q
        } else {
            O[row*Dc + t] = acc[r] + bb + P[(row & (Lc-1))*Dc + t];
        }
    }
}

// ---------------- K1c: dqt[row][h][tau] = Qs[row,h,:] . timeK[tau,h,:] ----------------
// [row][h][tau] layout: warp stores 32 consecutive taus -> fully coalesced 128B.
#define QTROWS 16
__global__ void __launch_bounds__(256, 4) k_qt(const float* __restrict__ timeK) {
    __shared__ __align__(16) float sQ[QTROWS*128];   // 8 KB
    int t = threadIdx.x;
    int w = t >> 5, lane = t & 31;
    int h = w & 3;
    int tau = blockIdx.y*64 + (w >> 2)*32 + lane;
    int r0 = blockIdx.x * QTROWS;
    bool valid = (tau < NTAU);

    float4 tr[8];
    if (valid) {
        const float4* src = (const float4*)&timeK[tau*128 + h*32];
        #pragma unroll
        for (int j = 0; j < 8; ++j) tr[j] = src[j];
    }

    { // stage 16 Q rows (coalesced): 512 float4
        const float4* src = (const float4*)&g_Q[r0*128];
        float4* dst = (float4*)sQ;
        dst[t] = src[t];
        dst[t + 256] = src[t + 256];
    }
    __syncthreads();
    if (valid) {
        for (int r = 0; r < QTROWS; r += 2) {
            const float4* qa = (const float4*)&sQ[r*128 + h*32];       // broadcast
            const float4* qb = (const float4*)&sQ[(r+1)*128 + h*32];   // broadcast
            float a0 = 0.f, a1 = 0.f, b0 = 0.f, b1 = 0.f;
            #pragma unroll
            for (int j = 0; j < 8; j += 2) {
                float4 qa0 = qa[j], qa1 = qa[j+1];
                float4 qb0 = qb[j], qb1 = qb[j+1];
                a0 += tr[j  ].x*qa0.x + tr[j  ].y*qa0.y + tr[j  ].z*qa0.z + tr[j  ].w*qa0.w;
                a1 += tr[j+1].x*qa1.x + tr[j+1].y*qa1.y + tr[j+1].z*qa1.z + tr[j+1].w*qa1.w;
                b0 += tr[j  ].x*qb0.x + tr[j  ].y*qb0.y + tr[j  ].z*qb0.z + tr[j  ].w*qb0.w;
                b1 += tr[j+1].x*qb1.x + tr[j+1].y*qb1.y + tr[j+1].z*qb1.z + tr[j+1].w*qb1.w;
            }
            g_dqt[(size_t)(r0 + r    )*DQR + h*NTAU + tau] = a0 + a1;   // coalesced
            g_dqt[(size_t)(r0 + r + 1)*DQR + h*NTAU + tau] = b0 + b1;
        }
    }
}

// ---------------- K2: tiled attention (pad-free, causal-truncated) ----------------
// Pass 3 streams Vc/timeV directly from global (coalesced, L1-hot) -> no barriers.
__global__ void __launch_bounds__(256) k_attn(const int* __restrict__ time_mat) {
    extern __shared__ __align__(16) char smem_raw[];
    float* sKV = (float*)smem_raw;                 // CH*PADK = 8448 (pass 1 only)
    float* sQ  = sKV + 8448;                       // TQ2*128 = 512
    float* sS  = sQ  + 512;                        // TQ2*4*256 = 4096
    int*   s_tm = (int*)(sS + 4096);               // TQ2*256 = 1024

    int t = threadIdx.x;                           // 256
    int b  = blockIdx.x >> 6;
    int q0 = (blockIdx.x & 63) * TQ2;
    int row0 = b*Lc + q0;
    int brow = b*Lc;

    { // Q tile: 512 floats = 128 float4
        if (t < 128) {
            const float4* src = (const float4*)&g_Q[row0*128];
            ((float4*)sQ)[t] = src[t];
        }
    }
    { // tm tile: 1024 ints = 256 int4
        const int4* src = (const int4*)&time_mat[row0*256];
        ((int4*)s_tm)[t] = src[t];
    }
    { // init sS = NEGV
        float4 negv = make_float4(NEGV, NEGV, NEGV, NEGV);
        float4* p = (float4*)sS;
        #pragma unroll
        for (int i = 0; i < 4; ++i) p[t + 256*i] = negv;
    }
    __syncthreads();

    int nkt = ((q0 + TQ2 - 1) >> 6) + 1;

    // ---- pass 1: scores (Q pre-scaled, causal only) ----
    {
        int q = t >> 6, kl = t & 63;
        const float* dqp = &g_dqt[(size_t)(row0 + q)*DQR];
        for (int kt = 0; kt < nkt; ++kt) {
            int k0 = kt * CH;
            { // coalesced load Kc chunk: 2048 float4
                const float4* src = (const float4*)&g_Kc[(brow + k0)*128];
                float4* dst = (float4*)sKV;
                #pragma unroll
                for (int j = 0; j < 8; ++j) {
                    int f4 = t + 256*j;
                    dst[(f4 >> 5)*33 + (f4 & 31)] = src[f4];
                }
            }
            __syncthreads();
            int kg = k0 + kl;
            if (kg <= q0 + q) {
                const float4* kr = (const float4*)&sKV[kl*PADK];
                const float4* qr = (const float4*)&sQ[q*128];   // broadcast
                float sc[4] = {0.f, 0.f, 0.f, 0.f};
                #pragma unroll
                for (int j = 0; j < 32; ++j) {
                    float4 kv = kr[j], qv = qr[j];
                    sc[j >> 3] += kv.x*qv.x + kv.y*qv.y + kv.z*qv.z + kv.w*qv.w;
                }
                int tau = s_tm[q*256 + kg];
                // 4 independent scalar loads, L1-hot (16 KB/block)
                sS[(q*4+0)*256 + kg] = sc[0] + dqp[tau];
                sS[(q*4+1)*256 + kg] = sc[1] + dqp[NTAU   + tau];
                sS[(q*4+2)*256 + kg] = sc[2] + dqp[2*NTAU + tau];
                sS[(q*4+3)*256 + kg] = sc[3] + dqp[3*NTAU + tau];
            }
            __syncthreads();
        }
    }

    // ---- pass 2: softmax (16 rows of 256; each warp handles 2 rows) ----
    {
        int w = t >> 5, lane = t & 31;
        #pragma unroll
        for (int j = 0; j < 2; ++j) {
            float* p = sS + (w + j*8)*256;
            float x[8];
            float mx = -3.4e38f;
            #pragma unroll
            for (int i = 0; i < 8; ++i) { x[i] = p[lane + 32*i]; mx = fmaxf(mx, x[i]); }
            #pragma unroll
            for (int o = 16; o >= 1; o >>= 1)
                mx = fmaxf(mx, __shfl_xor_sync(0xffffffffu, mx, o));
            float s = 0.f;
            #pragma unroll
            for (int i = 0; i < 8; ++i) { x[i] = expf(x[i] - mx); s += x[i]; }
            #pragma unroll
            for (int o = 16; o >= 1; o >>= 1)
                s += __shfl_xor_sync(0xffffffffu, s, o);
            float inv = 1.f / s;
            #pragma unroll
            for (int i = 0; i < 8; ++i) p[lane + 32*i] = x[i] * inv;
        }
    }
    __syncthreads();

    // ---- pass 3: out = A @ (Vc + timeV[bf16]); direct global streaming ----
    {
        int colp = (t & 63) * 2;      // even column; lanes -> 256B coalesced
        int q    = t >> 6;            // warp-uniform
        int h    = colp >> 5;
        int kend = q0 + q + 1;        // exact causal limit
        const float* sA  = sS + (q*4 + h)*256;
        const int*   tmq = s_tm + q*256;
        const float* vbase = &g_Vc[brow*128 + colp];
        float acc0 = 0.f, acc1 = 0.f;
        #pragma unroll 4
        for (int k = 0; k < kend; ++k) {
            float2 v2 = *(const float2*)&vbase[(size_t)k*128];
            float a = sA[k];                               // smem broadcast
            int tau = tmq[k];                              // smem broadcast
            __nv_bfloat162 tv2 = *(const __nv_bfloat162*)&g_tVb[tau*128 + colp];
            float2 tvf = __bfloat1622float2(tv2);
            acc0 = fmaf(a, v2.x + tvf.x, acc0);
            acc1 = fmaf(a, v2.y + tvf.y, acc1);
        }
        int idx = (row0 + q)*128 + colp;
        float2 qi = *(const float2*)&g_qin[idx];
        float2 o2 = make_float2(qi.x + acc0, qi.y + acc1);
        *(float2*)&g_seqs[idx] = o2;
    }
}

// ---------------- K3: LN2 + FFN + residual + pad-mask (+ LN1 of next layer) ----------------
__global__ void __launch_bounds__(128) k_ffn(const int* __restrict__ log_seqs,
                      const float* __restrict__ ln2_g, const float* __restrict__ ln2_b,
                      const float* __restrict__ W1, const float* __restrict__ b1,
                      const float* __restrict__ W2, const float* __restrict__ b2,
                      const float* __restrict__ ng, const float* __restrict__ nb) {
    __shared__ __align__(16) float s_y[RF][Dc];
    __shared__ __align__(16) float s_h[RF][Dc];
    __shared__ float s_mean[RF], s_inv[RF];
    __shared__ int   s_pad[RF];
    int t = threadIdx.x;
    int row0 = blockIdx.x * RF;
    int r = t >> 5, lane = t & 31;

    for (int i = t; i < RF*Dc; i += 128)
        ((float*)s_h)[i] = g_seqs[row0*Dc + i];
    if (t < RF) s_pad[t] = (log_seqs[row0 + t] == 0);
    __syncthreads();

    {
        float4 v4 = *(const float4*)&s_h[r][lane*4];
        float s  = v4.x + v4.y + v4.z + v4.w;
        float ss = v4.x*v4.x + v4.y*v4.y + v4.z*v4.z + v4.w*v4.w;
        #pragma unroll
        for (int o = 16; o >= 1; o >>= 1) {
            s  += __shfl_xor_sync(0xffffffffu, s,  o);
            ss += __shfl_xor_sync(0xffffffffu, ss, o);
        }
        if (lane == 0) {
            float m = s * (1.f/Dc);
            float var = ss * (1.f/Dc) - m*m;
            s_mean[r] = m;
            s_inv[r]  = rsqrtf(var + 1e-8f);
        }
    }
    __syncthreads();

    float g = ln2_g[t], bb = ln2_b[t];
    #pragma unroll
    for (int rr = 0; rr < RF; ++rr)
        s_y[rr][t] = (s_h[rr][t] - s_mean[rr]) * s_inv[rr] * g + bb;
    __syncthreads();

    float a1[RF];
    #pragma unroll
    for (int rr = 0; rr < RF; ++rr) a1[rr] = 0.f;
    for (int k = 0; k < Dc; k += 4) {
        float w0=W1[(k+0)*Dc+t], w1=W1[(k+1)*Dc+t], w2=W1[(k+2)*Dc+t], w3=W1[(k+3)*Dc+t];
        #pragma unroll
        for (int rr = 0; rr < RF; ++rr) {
            float4 y = *(const float4*)&s_y[rr][k];
            a1[rr] = fmaf(y.x,w0, fmaf(y.y,w1, fmaf(y.z,w2, fmaf(y.w,w3, a1[rr]))));
        }
    }
    float b1v = b1[t];
    __syncthreads();
    #pragma unroll
    for (int rr = 0; rr < RF; ++rr)
        s_h[rr][t] = fmaxf(a1[rr] + b1v, 0.f);
    __syncthreads();

    float a2[RF];
    #pragma unroll
    for (int rr = 0; rr < RF; ++rr) a2[rr] = 0.f;
    for (int k = 0; k < Dc; k += 4) {
        float w0=W2[(k+0)*Dc+t], w1=W2[(k+1)*Dc+t], w2=W2[(k+2)*Dc+t], w3=W2[(k+3)*Dc+t];
        #pragma unroll
        for (int rr = 0; rr < RF; ++rr) {
            float4 h4 = *(const float4*)&s_h[rr][k];
            a2[rr] = fmaf(h4.x,w0, fmaf(h4.y,w1, fmaf(h4.z,w2, fmaf(h4.w,w3, a2[rr]))));
        }
    }
    float b2v = b2[t];
    float vout[RF];
    #pragma unroll
    for (int rr = 0; rr < RF; ++rr) {
        vout[rr] = s_pad[rr] ? 0.f : (s_y[rr][t] + a2[rr] + b2v);
        g_seqs[(row0 + rr)*Dc + t] = vout[rr];
    }

    if (ng) {  // LN1 of next layer, fused
        __syncthreads();
        #pragma unroll
        for (int rr = 0; rr < RF; ++rr) s_h[rr][t] = vout[rr];
        __syncthreads();
        {
            float4 v4 = *(const float4*)&s_h[r][lane*4];
            float s  = v4.x + v4.y + v4.z + v4.w;
            float ss = v4.x*v4.x + v4.y*v4.y + v4.z*v4.z + v4.w*v4.w;
            #pragma unroll
            for (int o = 16; o >= 1; o >>= 1) {
                s  += __shfl_xor_sync(0xffffffffu, s,  o);
                ss += __shfl_xor_sync(0xffffffffu, ss, o);
            }
            if (lane == 0) {
                float m = s * (1.f/Dc);
                float var = ss * (1.f/Dc) - m*m;
                s_mean[r] = m;
                s_inv[r]  = rsqrtf(var + 1e-8f);
            }
        }
        __syncthreads();
        float gg = ng[t], bb2 = nb[t];
        #pragma unroll
        for (int rr = 0; rr < RF; ++rr)
            g_qin[(row0 + rr)*Dc + t] = (s_h[rr][t] - s_mean[rr]) * s_inv[rr] * gg + bb2;
    }
}

// ---------------- K4: final LN + pos/neg logits ----------------
__global__ void __launch_bounds__(128) k_logits(
                         const int* __restrict__ pos_seqs, const int* __restrict__ neg_seqs,
                         const float* __restrict__ item_emb,
                         const float* __restrict__ lnf_g, const float* __restrict__ lnf_b,
                         float* __restrict__ out) {
    __shared__ float r1[4], r2[4];
    int row = blockIdx.x, t = threadIdx.x;
    int warp = t >> 5, lane = t & 31;

    float x = g_seqs[row*Dc + t];
    float s = x, ss = x*x;
    #pragma unroll
    for (int o = 16; o >= 1; o >>= 1) {
        s  += __shfl_xor_sync(0xffffffffu, s,  o);
        ss += __shfl_xor_sync(0xffffffffu, ss, o);
    }
    if (lane == 0) { r1[warp] = s; r2[warp] = ss; }
    __syncthreads();
    float tot  = r1[0]+r1[1]+r1[2]+r1[3];
    float tots = r2[0]+r2[1]+r2[2]+r2[3];
    float m = tot * (1.f/Dc);
    float inv = rsqrtf(tots * (1.f/Dc) - m*m + 1e-8f);
    float f = (x - m) * inv * lnf_g[t] + lnf_b[t];

    int pi = pos_seqs[row], ni = neg_seqs[row];
    float pp = f * item_emb[pi*Dc + t];
    float nn = f * item_emb[ni*Dc + t];
    #pragma unroll
    for (int o = 16; o >= 1; o >>= 1) {
        pp += __shfl_xor_sync(0xffffffffu, pp, o);
        nn += __shfl_xor_sync(0xffffffffu, nn, o);
    }
    __syncthreads();
    if (lane == 0) { r1[warp] = pp; r2[warp] = nn; }
    __syncthreads();
    if (t == 0) {
        out[row]        = r1[0]+r1[1]+r1[2]+r1[3];
        out[NROW + row] = r2[0]+r2[1]+r2[2]+r2[3];
    }
}

// ---------------- launch ----------------
extern "C" void kernel_launch(void* const* d_in, const int* in_sizes, int n_in,
                              void* d_out, int out_size) {
    const int*   log_seqs = (const int*)  d_in[1];
    const int*   time_mat = (const int*)  d_in[2];
    const int*   pos_seqs = (const int*)  d_in[3];
    const int*   neg_seqs = (const int*)  d_in[4];
    const float* item_emb = (const float*)d_in[5];
    const float* posK     = (const float*)d_in[6];
    const float* posV     = (const float*)d_in[7];
    const float* timeK    = (const float*)d_in[8];
    const float* timeV    = (const float*)d_in[9];
    const float* ln1_g    = (const float*)d_in[10];
    const float* ln1_b    = (const float*)d_in[11];
    const float* Wq       = (const float*)d_in[12];
    const float* bq       = (const float*)d_in[13];
    const float* Wk       = (const float*)d_in[14];
    const float* bk       = (const float*)d_in[15];
    const float* Wv       = (const float*)d_in[16];
    const float* bv       = (const float*)d_in[17];
    const float* ln2_g    = (const float*)d_in[18];
    const float* ln2_b    = (const float*)d_in[19];
    const float* W1       = (const float*)d_in[20];
    const float* b1       = (const float*)d_in[21];
    const float* W2       = (const float*)d_in[22];
    const float* b2       = (const float*)d_in[23];
    const float* lnf_g    = (const float*)d_in[24];
    const float* lnf_b    = (const float*)d_in[25];
    float* out = (float*)d_out;

    cudaFuncSetAttribute(k_attn, cudaFuncAttributeMaxDynamicSharedMemorySize, SMEM_ATTN);

    k_embed<<<NROW + CVTB, 128>>>(log_seqs, item_emb, ln1_g, ln1_b, timeV);
    for (int i = 0; i < 2; ++i) {
        dim3 gq(NROW/RQ, 3);
        k_qkv<<<gq, 128>>>(Wq + i*Dc*Dc, Wk + i*Dc*Dc, Wv + i*Dc*Dc,
                           bq + i*Dc, bk + i*Dc, bv + i*Dc, posK, posV);
        dim3 gt(NROW/QTROWS, 5);          // (128, 5) = 640 blocks
        k_qt<<<gt, 256>>>(timeK);
        k_attn<<<NROW/TQ2, 256, SMEM_ATTN>>>(time_mat);
        const float* ng = (i == 0) ? (ln1_g + Dc) : nullptr;
        const float* nb = (i == 0) ? (ln1_b + Dc) : nullptr;
        k_ffn<<<NROW/RF, 128>>>(log_seqs, ln2_g + i*Dc, ln2_b + i*Dc,
                                W1 + i*Dc*Dc, b1 + i*Dc,
                                W2 + i*Dc*Dc, b2 + i*Dc, ng, nb);
    }
    k_logits<<<NROW, 128>>>(pos_seqs, neg_seqs, item_emb, lnf_g, lnf_b, out);
}